// round 15
// baseline (speedup 1.0000x reference)
#include <cuda_runtime.h>
#include <cuda_fp16.h>
#include <stdint.h>
#include <math.h>

#define DEVFN __device__ __forceinline__

static constexpr int NNODE = 4096, DIM = 128;
static constexpr int NU = 100000, NR = 32, NA = 5000;

// ---- device scratch ----
__device__ __align__(16) __half g_R12h  [64 * 256];        // fp16 R12 rows (incl b1 in rows 0-31)
__device__ __align__(16) float  g_selfA1[NNODE * DIM];
__device__ __align__(16) __half g_U1 [(size_t)NU * 256];   // u2e @ W1[256:384]  (51.2 MB)
__device__ __align__(16) __half g_A1t[(size_t)NA * 256];   // ua2e @ W1[384:512]
// B fragments, paired layout: uint4 per (ks, np, lane)
__device__ __align__(16) uint2  g_FU1a[8 * 16 * 32];       // W1[256:384] cols 0-127
__device__ __align__(16) uint2  g_FU1b[8 * 16 * 32];       // cols 128-255
__device__ __align__(16) uint2  g_FA1a[8 * 16 * 32];       // W1[384:512] cols 0-127
__device__ __align__(16) uint2  g_FA1b[8 * 16 * 32];       // cols 128-255
__device__ __align__(16) uint2  g_FG2[16 * 16 * 32];       // K=256
__device__ __align__(16) uint2  g_FG3[8 * 16 * 32];        // K=128
__device__ __align__(16) uint2  g_FG4[8 * 16 * 32];        // K=128

// ---- smem layout (bytes) ----
static constexpr uint32_t OFF_B2S = 0, OFF_AB2 = 512, OFF_A3 = 1024, OFF_SA = 1536,
    OFF_LG = 2560, OFF_LGP = 3072, OFF_WGT = 5120, OFF_OUT = 5632, OFF_AB3 = 6656,
    OFF_XB = 6912;
static constexpr int XS = 264;                        // X stride (halfs)
static constexpr uint32_t SMEM_BYTES = OFF_XB + 128 * XS * 2;   // 74496

// ---- PTX helpers ----
DEVFN uint32_t smem_u32(const void* p) {
    uint32_t a;
    asm("{ .reg .u64 t; cvta.to.shared.u64 t, %1; cvt.u32.u64 %0, t; }" : "=r"(a) : "l"(p));
    return a;
}
DEVFN void ldm4(uint32_t* r, uint32_t a) {
    asm volatile("ldmatrix.sync.aligned.m8n8.x4.shared.b16 {%0,%1,%2,%3}, [%4];"
                 : "=r"(r[0]), "=r"(r[1]), "=r"(r[2]), "=r"(r[3]) : "r"(a));
}
DEVFN void mma16816(float* c, const uint32_t* a, uint32_t b0, uint32_t b1) {
    asm volatile("mma.sync.aligned.m16n8k16.row.col.f32.f16.f16.f32 "
                 "{%0,%1,%2,%3}, {%4,%5,%6,%7}, {%8,%9}, {%0,%1,%2,%3};"
                 : "+f"(c[0]), "+f"(c[1]), "+f"(c[2]), "+f"(c[3])
                 : "r"(a[0]), "r"(a[1]), "r"(a[2]), "r"(a[3]), "r"(b0), "r"(b1));
}
DEVFN uint32_t pack2(float a, float b) {
    __half2 h = __floats2half2_rn(a, b);
    return *(uint32_t*)&h;
}

// single GEMM, paired-uint4 B fragments, register double-buffered prefetch
// 16 warps 4x4: mg 32 rows, ng 32 cols (4 nt); A stride AST halfs
template<int K, int AST>
DEVFN void gemm_tile(uint32_t aXbase, const uint2* __restrict__ F,
                     float (&acc)[2][4][4], int lane, int mg, int ng) {
    constexpr int KS = K / 16;
    uint32_t aA = aXbase + (uint32_t)((mg * 32 + ((lane >> 3) & 1) * 8 + (lane & 7)) * AST
                                      + (lane >> 4) * 8) * 2;
    const uint4* Fw = (const uint4*)F + (ng * 2) * 32 + lane;
    #pragma unroll
    for (int m = 0; m < 2; m++)
        #pragma unroll
        for (int n = 0; n < 4; n++)
            #pragma unroll
            for (int e = 0; e < 4; e++) acc[m][n][e] = 0.f;
    uint4 bf[2], bn[2];
    #pragma unroll
    for (int j = 0; j < 2; j++) bf[j] = __ldg(Fw + j * 32);
    #pragma unroll 1
    for (int ks = 0; ks < KS; ks++) {
        if (ks + 1 < KS) {
            #pragma unroll
            for (int j = 0; j < 2; j++) bn[j] = __ldg(Fw + (ks + 1) * 256 + j * 32);
        }
        uint32_t a0[4], a1[4];
        ldm4(a0, aA + ks * 32);
        ldm4(a1, aA + 16 * AST * 2 + ks * 32);
        #pragma unroll
        for (int j = 0; j < 2; j++) {
            mma16816(acc[0][2 * j],     a0, bf[j].x, bf[j].y);
            mma16816(acc[1][2 * j],     a1, bf[j].x, bf[j].y);
            mma16816(acc[0][2 * j + 1], a0, bf[j].z, bf[j].w);
            mma16816(acc[1][2 * j + 1], a1, bf[j].z, bf[j].w);
        }
        #pragma unroll
        for (int j = 0; j < 2; j++) bf[j] = bn[j];
    }
}

// dual GEMM (shared A fragments, two B tables), paired + prefetched
template<int K, int AST>
DEVFN void gemm_dual(uint32_t aXbase, const uint2* __restrict__ F0,
                     const uint2* __restrict__ F1,
                     float (&acc1)[2][4][4], float (&acc2)[2][4][4],
                     int lane, int mg, int ng) {
    constexpr int KS = K / 16;
    uint32_t aA = aXbase + (uint32_t)((mg * 32 + ((lane >> 3) & 1) * 8 + (lane & 7)) * AST
                                      + (lane >> 4) * 8) * 2;
    const uint4* Fw0 = (const uint4*)F0 + (ng * 2) * 32 + lane;
    const uint4* Fw1 = (const uint4*)F1 + (ng * 2) * 32 + lane;
    #pragma unroll
    for (int m = 0; m < 2; m++)
        #pragma unroll
        for (int n = 0; n < 4; n++)
            #pragma unroll
            for (int e = 0; e < 4; e++) { acc1[m][n][e] = 0.f; acc2[m][n][e] = 0.f; }
    uint4 bf0[2], bf1[2], bn0[2], bn1[2];
    #pragma unroll
    for (int j = 0; j < 2; j++) { bf0[j] = __ldg(Fw0 + j * 32); bf1[j] = __ldg(Fw1 + j * 32); }
    #pragma unroll 1
    for (int ks = 0; ks < KS; ks++) {
        if (ks + 1 < KS) {
            #pragma unroll
            for (int j = 0; j < 2; j++) {
                bn0[j] = __ldg(Fw0 + (ks + 1) * 256 + j * 32);
                bn1[j] = __ldg(Fw1 + (ks + 1) * 256 + j * 32);
            }
        }
        uint32_t a0[4], a1[4];
        ldm4(a0, aA + ks * 32);
        ldm4(a1, aA + 16 * AST * 2 + ks * 32);
        #pragma unroll
        for (int j = 0; j < 2; j++) {
            mma16816(acc1[0][2 * j],     a0, bf0[j].x, bf0[j].y);
            mma16816(acc1[1][2 * j],     a1, bf0[j].x, bf0[j].y);
            mma16816(acc1[0][2 * j + 1], a0, bf0[j].z, bf0[j].w);
            mma16816(acc1[1][2 * j + 1], a1, bf0[j].z, bf0[j].w);
            mma16816(acc2[0][2 * j],     a0, bf1[j].x, bf1[j].y);
            mma16816(acc2[1][2 * j],     a1, bf1[j].x, bf1[j].y);
            mma16816(acc2[0][2 * j + 1], a0, bf1[j].z, bf1[j].w);
            mma16816(acc2[1][2 * j + 1], a1, bf1[j].z, bf1[j].w);
        }
        #pragma unroll
        for (int j = 0; j < 2; j++) { bf0[j] = bn0[j]; bf1[j] = bn1[j]; }
    }
}

// ===== prepass 1: r12 (64) || selfA1 (512) || pack tables (128) =====
__global__ void k_prep(const float* __restrict__ u2e, const float* __restrict__ r2e,
                       const float* __restrict__ W1, const float* __restrict__ b1,
                       const int* __restrict__ nodes, const float* __restrict__ A1,
                       const float* __restrict__ ab1, const float* __restrict__ W2,
                       const float* __restrict__ A2) {
    __shared__ float sh[8 * 128];
    int b = blockIdx.x, tid = threadIdx.x;
    if (b < 64) {                       // r12: b = t*32+i -> fp16 R12h row (stride 256)
        int t = b >> 5, i = b & 31, c = tid;
        if (c < 128) sh[c] = r2e[i * 128 + c];
        __syncthreads();
        float acc = (t == 0) ? b1[c] : 0.f;
        #pragma unroll 4
        for (int k = 0; k < 128; k++) acc += sh[k] * W1[(t * 128 + k) * 256 + c];
        g_R12h[(t * 32 + i) * 256 + c] = __float2half_rn(acc);
    } else if (b < 576) {               // selfA1: warp-per-node, 512 blocks x 8 warps
        int w = tid >> 5, lane = tid & 31;
        int n = (b - 64) * 8 + w, nd = nodes[n];
        *(float4*)&sh[w * 128 + lane * 4] = *(const float4*)(u2e + (size_t)nd * 128 + lane * 4);
        __syncwarp();
        float4 acc = *(const float4*)(ab1 + lane * 4);
        const float4* A1b = (const float4*)(A1 + 16384) + lane;
        #pragma unroll 8
        for (int k = 0; k < 128; k++) {
            float s = sh[w * 128 + k];
            float4 a4 = __ldg(A1b + k * 32);
            acc.x += s * a4.x; acc.y += s * a4.y; acc.z += s * a4.z; acc.w += s * a4.w;
        }
        *(float4*)(g_selfA1 + (size_t)n * 128 + lane * 4) = acc;
    } else {                            // pack: 128 blocks x 256 = 32768 ids
        int id = (b - 576) * 256 + tid;
        int table, rem;
        if (id < 16384)      { table = id >> 12; rem = id & 4095; }          // 0-3: FU1a/FU1b/FA1a/FA1b
        else if (id < 24576) { table = 4; rem = id - 16384; }                // FG2
        else if (id < 28672) { table = 5; rem = id - 24576; }                // FG3
        else                 { table = 6; rem = id - 28672; }                // FG4
        int lane = rem & 31, nb = (rem >> 5) & 15, ks = rem >> 9;
        int n = nb * 8 + (lane >> 2), k0 = ks * 16 + (lane & 3) * 2;
        float v[4];
        #pragma unroll
        for (int j = 0; j < 4; j++) {
            int k = k0 + (j >> 1) * 8 + (j & 1);
            float val;
            if (table < 4) {
                int kb = (table < 2) ? 256 : 384;
                int nc = (table & 1) ? n + 128 : n;
                val = W1[(kb + k) * 256 + nc];
            } else if (table == 4) val = W2[k * 128 + n];
            else if (table == 5)   val = A1[k * 128 + n];
            else                   val = A2[k * 128 + n];
            v[j] = val;
        }
        uint2 fr = make_uint2(pack2(v[0], v[1]), pack2(v[2], v[3]));
        int sidx = ks * 512 + (nb >> 1) * 64 + lane * 2 + (nb & 1);
        if (table == 0)      g_FU1a[sidx] = fr;
        else if (table == 1) g_FU1b[sidx] = fr;
        else if (table == 2) g_FA1a[sidx] = fr;
        else if (table == 3) g_FA1b[sidx] = fr;
        else if (table == 4) g_FG2[sidx] = fr;
        else if (table == 5) g_FG3[sidx] = fr;
        else                 g_FG4[sidx] = fr;
    }
}

// ===== prepass 2: table GEMMs  U1 = u2e@W1[256:384], A1t = ua2e@W1[384:512] =====
__global__ void __launch_bounds__(512, 1)
k_u1(const float* __restrict__ u2e, const float* __restrict__ ua2e) {
    __shared__ __half At[128 * 136];
    int b = blockIdx.x, tid = threadIdx.x, wid = tid >> 5, lane = tid & 31;
    int mg = wid >> 2, ng = wid & 3;
    const float* Asrc; __half* Out; int nrows, rbase;
    const uint2 *F0, *F1;
    if (b < 782) { Asrc = u2e;  Out = g_U1;  nrows = NU; rbase = b * 128;
                   F0 = g_FU1a; F1 = g_FU1b; }
    else         { Asrc = ua2e; Out = g_A1t; nrows = NA; rbase = (b - 782) * 128;
                   F0 = g_FA1a; F1 = g_FA1b; }
    #pragma unroll 1
    for (int s = 0; s < 8; s++) {
        int r = wid * 8 + s;
        int gr = rbase + r; if (gr >= nrows) gr = nrows - 1;
        float4 v = __ldg((const float4*)(Asrc + (size_t)gr * 128) + lane);
        *(uint2*)(&At[r * 136 + lane * 4]) = make_uint2(pack2(v.x, v.y), pack2(v.z, v.w));
    }
    __syncthreads();
    float acc1[2][4][4], acc2[2][4][4];
    gemm_dual<128, 136>(smem_u32(At), F0, F1, acc1, acc2, lane, mg, ng);
    #pragma unroll
    for (int mf = 0; mf < 2; mf++) {
        int row = mg * 32 + mf * 16 + (lane >> 2);
        int g0 = rbase + row, g1 = g0 + 8;
        #pragma unroll
        for (int nt = 0; nt < 4; nt++) {
            int col = ng * 32 + nt * 8 + (lane & 3) * 2;
            if (g0 < nrows) {
                *(__half2*)(Out + (size_t)g0 * 256 + col)       = __floats2half2_rn(acc1[mf][nt][0], acc1[mf][nt][1]);
                *(__half2*)(Out + (size_t)g0 * 256 + col + 128) = __floats2half2_rn(acc2[mf][nt][0], acc2[mf][nt][1]);
            }
            if (g1 < nrows) {
                *(__half2*)(Out + (size_t)g1 * 256 + col)       = __floats2half2_rn(acc1[mf][nt][2], acc1[mf][nt][3]);
                *(__half2*)(Out + (size_t)g1 * 256 + col + 128) = __floats2half2_rn(acc2[mf][nt][2], acc2[mf][nt][3]);
            }
        }
    }
}

// ================= main fused kernel =================
__global__ void __launch_bounds__(512, 1)
k_main(const int* __restrict__ prel, const int* __restrict__ pnbr,
       const int* __restrict__ attrs,
       const float* __restrict__ b2, const float* __restrict__ ab2,
       const float* __restrict__ A3, const float* __restrict__ ab3,
       float* __restrict__ out) {
    extern __shared__ char sm[];
    const uint32_t sb = smem_u32(sm);
    const int tid = threadIdx.x, wid = tid >> 5, lane = tid & 31;
    const int mg = wid >> 2, ng = wid & 3;
    const int tile = blockIdx.x;

    float* b2s  = (float*)(sm + OFF_B2S);
    float* ab2s = (float*)(sm + OFF_AB2);
    float* A3s  = (float*)(sm + OFF_A3);
    float* SA   = (float*)(sm + OFF_SA);
    float* LG   = (float*)(sm + OFF_LG);
    float* LGP  = (float*)(sm + OFF_LGP);
    float* wgs  = (float*)(sm + OFF_WGT);
    float* OUTa = (float*)(sm + OFF_OUT);
    char*  XB   = sm + OFF_XB;
    const uint32_t aXB = sb + OFF_XB;

    if (tid < 128) { b2s[tid] = b2[tid]; ab2s[tid] = ab2[tid]; A3s[tid] = A3[tid]; }
    if (tid == 0) *(float*)(sm + OFF_AB3) = ab3[0];
    if (tid < 256) { SA[tid] = g_selfA1[(size_t)tile * 256 + tid]; OUTa[tid] = 0.f; }

    // ---- gather h1 directly: h1 = relu(U1[nbr] + sum8 A1t[at] + R12[r0] + R12[32+r1]) ----
    {
        const int rbase = wid * 8;
        #pragma unroll 1
        for (int s8 = 0; s8 < 8; s8++) {
            int row = rbase + s8, p = tile * 128 + row;
            char* XR = XB + row * (XS * 2);
            int u = __ldg(pnbr + p);
            const int4* ap = (const int4*)(attrs + (size_t)p * 8);
            int4 a0v = __ldg(ap), a1v = __ldg(ap + 1);
            int r0 = __ldg(prel + p * 2), r1 = __ldg(prel + p * 2 + 1);
            uint4 sv[11];
            sv[0] = __ldg((const uint4*)(g_U1 + (size_t)u * 256) + lane);
            sv[1] = __ldg((const uint4*)(g_A1t + (size_t)a0v.x * 256) + lane);
            sv[2] = __ldg((const uint4*)(g_A1t + (size_t)a0v.y * 256) + lane);
            sv[3] = __ldg((const uint4*)(g_A1t + (size_t)a0v.z * 256) + lane);
            sv[4] = __ldg((const uint4*)(g_A1t + (size_t)a0v.w * 256) + lane);
            sv[5] = __ldg((const uint4*)(g_A1t + (size_t)a1v.x * 256) + lane);
            sv[6] = __ldg((const uint4*)(g_A1t + (size_t)a1v.y * 256) + lane);
            sv[7] = __ldg((const uint4*)(g_A1t + (size_t)a1v.z * 256) + lane);
            sv[8] = __ldg((const uint4*)(g_A1t + (size_t)a1v.w * 256) + lane);
            sv[9]  = __ldg((const uint4*)(g_R12h + r0 * 256) + lane);
            sv[10] = __ldg((const uint4*)(g_R12h + (32 + r1) * 256) + lane);
            float2 s0 = make_float2(0.f, 0.f), s1 = s0, s2 = s0, s3 = s0;
            #pragma unroll
            for (int a = 0; a < 11; a++) {
                float2 f0 = __half22float2(*(__half2*)&sv[a].x);
                float2 f1 = __half22float2(*(__half2*)&sv[a].y);
                float2 f2 = __half22float2(*(__half2*)&sv[a].z);
                float2 f3 = __half22float2(*(__half2*)&sv[a].w);
                s0.x += f0.x; s0.y += f0.y; s1.x += f1.x; s1.y += f1.y;
                s2.x += f2.x; s2.y += f2.y; s3.x += f3.x; s3.y += f3.y;
            }
            uint4 o;
            o.x = pack2(fmaxf(s0.x, 0.f), fmaxf(s0.y, 0.f));
            o.y = pack2(fmaxf(s1.x, 0.f), fmaxf(s1.y, 0.f));
            o.z = pack2(fmaxf(s2.x, 0.f), fmaxf(s2.y, 0.f));
            o.w = pack2(fmaxf(s3.x, 0.f), fmaxf(s3.y, 0.f));
            *(uint4*)(XR + lane * 16) = o;
        }
    }
    __syncthreads();

    float acc1[2][4][4], acc2[2][4][4];

    // G2: h1 @ W2' -> acc2 = h pre-bias (fp32, kept in regs)
    gemm_tile<256, XS>(aXB, g_FG2, acc2, lane, mg, ng);
    __syncthreads();

    // epilogue2: h = relu(acc2 + b2); keep fp32 in acc2, write fp16 XB cols 0-127
    #pragma unroll
    for (int mf = 0; mf < 2; mf++) {
        int row = mg * 32 + mf * 16 + (lane >> 2);
        #pragma unroll
        for (int nt = 0; nt < 4; nt++) {
            int col = ng * 32 + nt * 8 + (lane & 3) * 2;
            float v0 = fmaxf(acc2[mf][nt][0] + b2s[col],     0.f);
            float v1 = fmaxf(acc2[mf][nt][1] + b2s[col + 1], 0.f);
            float v2 = fmaxf(acc2[mf][nt][2] + b2s[col],     0.f);
            float v3 = fmaxf(acc2[mf][nt][3] + b2s[col + 1], 0.f);
            acc2[mf][nt][0] = v0; acc2[mf][nt][1] = v1;
            acc2[mf][nt][2] = v2; acc2[mf][nt][3] = v3;
            *(__half2*)(XB + (row * XS + col) * 2)       = __floats2half2_rn(v0, v1);
            *(__half2*)(XB + ((row + 8) * XS + col) * 2) = __floats2half2_rn(v2, v3);
        }
    }
    __syncthreads();
    // G3: h @ A1top -> acc1
    gemm_tile<128, XS>(aXB, g_FG3, acc1, lane, mg, ng);

    // epilogue3: a1 = relu(acc1 + selfA1[node]) -> fp16 XB cols 128-255
    {
        int node = mg >> 1;
        #pragma unroll
        for (int mf = 0; mf < 2; mf++) {
            int row = mg * 32 + mf * 16 + (lane >> 2);
            #pragma unroll
            for (int nt = 0; nt < 4; nt++) {
                int col = ng * 32 + nt * 8 + (lane & 3) * 2;
                float s0 = SA[node * 128 + col], s1 = SA[node * 128 + col + 1];
                *(__half2*)(XB + (row * XS + col + 128) * 2) =
                    __floats2half2_rn(fmaxf(acc1[mf][nt][0] + s0, 0.f),
                                      fmaxf(acc1[mf][nt][1] + s1, 0.f));
                *(__half2*)(XB + ((row + 8) * XS + col + 128) * 2) =
                    __floats2half2_rn(fmaxf(acc1[mf][nt][2] + s0, 0.f),
                                      fmaxf(acc1[mf][nt][3] + s1, 0.f));
            }
        }
    }
    __syncthreads();
    // G4: a1 @ A2 -> acc1
    gemm_tile<128, XS>(aXB + 256, g_FG4, acc1, lane, mg, ng);

    // epilogue4: a2 = relu(acc1 + ab2); logit partials
    {
        float lp[4] = {0.f, 0.f, 0.f, 0.f};
        #pragma unroll
        for (int mf = 0; mf < 2; mf++)
            #pragma unroll
            for (int nt = 0; nt < 4; nt++) {
                int col = ng * 32 + nt * 8 + (lane & 3) * 2;
                float a30 = A3s[col], a31 = A3s[col + 1];
                float c0 = ab2s[col], c1 = ab2s[col + 1];
                lp[mf * 2 + 0] += fmaxf(acc1[mf][nt][0] + c0, 0.f) * a30
                                + fmaxf(acc1[mf][nt][1] + c1, 0.f) * a31;
                lp[mf * 2 + 1] += fmaxf(acc1[mf][nt][2] + c0, 0.f) * a30
                                + fmaxf(acc1[mf][nt][3] + c1, 0.f) * a31;
            }
        #pragma unroll
        for (int j = 0; j < 4; j++) {
            lp[j] += __shfl_xor_sync(0xffffffffu, lp[j], 1);
            lp[j] += __shfl_xor_sync(0xffffffffu, lp[j], 2);
        }
        if ((lane & 3) == 0) {
            int rbase = mg * 32 + (lane >> 2);
            #pragma unroll
            for (int j = 0; j < 4; j++)
                LGP[ng * 128 + rbase + j * 8] = lp[j];
        }
    }
    __syncthreads();
    if (tid < 128)
        LG[tid] = LGP[tid] + LGP[128 + tid] + LGP[256 + tid] + LGP[384 + tid]
                + *(float*)(sm + OFF_AB3);
    __syncthreads();
    if (wid < 2) {   // softmax per node over its 64 logits
        float a = LG[wid * 64 + lane], b = LG[wid * 64 + 32 + lane];
        float m = fmaxf(a, b);
        #pragma unroll
        for (int o = 16; o; o >>= 1) m = fmaxf(m, __shfl_xor_sync(0xffffffffu, m, o));
        float e1 = __expf(a - m), e2 = __expf(b - m), s = e1 + e2;
        #pragma unroll
        for (int o = 16; o; o >>= 1) s += __shfl_xor_sync(0xffffffffu, s, o);
        wgs[wid * 64 + lane] = e1 / s; wgs[wid * 64 + 32 + lane] = e2 / s;
    }
    __syncthreads();

    // weighted reduce: out[node][col] = sum_r wgs[r] * h[r][col]  (h fp32 in acc2)
    {
        float p[8];
        #pragma unroll
        for (int i = 0; i < 8; i++) p[i] = 0.f;
        #pragma unroll
        for (int mf = 0; mf < 2; mf++) {
            int r0 = mg * 32 + mf * 16 + (lane >> 2);
            float w0 = wgs[r0], w1 = wgs[r0 + 8];
            #pragma unroll
            for (int nt = 0; nt < 4; nt++) {
                p[nt * 2 + 0] += w0 * acc2[mf][nt][0] + w1 * acc2[mf][nt][2];
                p[nt * 2 + 1] += w0 * acc2[mf][nt][1] + w1 * acc2[mf][nt][3];
            }
        }
        #pragma unroll
        for (int i = 0; i < 8; i++) {
            p[i] += __shfl_xor_sync(0xffffffffu, p[i], 4);
            p[i] += __shfl_xor_sync(0xffffffffu, p[i], 8);
            p[i] += __shfl_xor_sync(0xffffffffu, p[i], 16);
        }
        if (lane < 4) {
            int node = mg >> 1;
            #pragma unroll
            for (int i = 0; i < 8; i++) {
                int col = ng * 32 + (i >> 1) * 8 + lane * 2 + (i & 1);
                atomicAdd(&OUTa[node * 128 + col], p[i]);
            }
        }
    }
    __syncthreads();
    if (tid < 256) out[(size_t)tile * 256 + tid] = OUTa[tid];
}

// ================= launch =================
extern "C" void kernel_launch(void* const* d_in, const int* in_sizes, int n_in,
                              void* d_out, int out_size) {
    const int*   nodes = (const int*)  d_in[0];
    const int*   prel  = (const int*)  d_in[1];
    const int*   pnbr  = (const int*)  d_in[2];
    const int*   attrs = (const int*)  d_in[3];
    const float* u2e   = (const float*)d_in[4];
    const float* r2e   = (const float*)d_in[5];
    const float* ua2e  = (const float*)d_in[6];
    const float* W1    = (const float*)d_in[7];
    const float* b1    = (const float*)d_in[8];
    const float* W2    = (const float*)d_in[9];
    const float* b2    = (const float*)d_in[10];
    const float* A1    = (const float*)d_in[11];
    const float* ab1   = (const float*)d_in[12];
    const float* A2    = (const float*)d_in[13];
    const float* ab2   = (const float*)d_in[14];
    const float* A3    = (const float*)d_in[15];
    const float* ab3   = (const float*)d_in[16];
    float* out = (float*)d_out;

    cudaFuncSetAttribute(k_main, cudaFuncAttributeMaxDynamicSharedMemorySize, (int)SMEM_BYTES);

    k_prep<<<704, 256>>>(u2e, r2e, W1, b1, nodes, A1, ab1, W2, A2);
    k_u1<<<822, 512>>>(u2e, ua2e);
    k_main<<<2048, 512, SMEM_BYTES>>>(prel, pnbr, attrs, b2, ab2, A3, ab3, out);
}

// round 16
// speedup vs baseline: 1.1943x; 1.1943x over previous
#include <cuda_runtime.h>
#include <cuda_fp16.h>
#include <stdint.h>
#include <math.h>

#define DEVFN __device__ __forceinline__

static constexpr int NNODE = 4096, DIM = 128;
static constexpr int NU = 100000, NR = 32, NA = 5000;

// ---- device scratch ----
__device__ __align__(16) __half g_ua2e_h[NA * DIM];
__device__ __align__(16) __half g_R12h  [64 * 256];       // fp16 R12 rows (b1 folded in rows 0-31)
__device__ __align__(16) float  g_selfA1[NNODE * DIM];
// B fragments, paired layout: uint4 per (ks, np, lane) = frags for nb=2np, 2np+1
__device__ __align__(16) uint2  g_FG1[2 * 16 * 16 * 32];  // K=256, two n-halves
__device__ __align__(16) uint2  g_FG2[16 * 16 * 32];      // K=256 (split-K usable: +4096 = ks 8..15)
__device__ __align__(16) uint2  g_FG3[8 * 16 * 32];       // K=128
__device__ __align__(16) uint2  g_FG4[8 * 16 * 32];       // K=128

// ---- smem layout (bytes) ----
static constexpr uint32_t OFF_B2S = 0, OFF_AB2 = 512, OFF_A3 = 1024, OFF_SA = 1536,
    OFF_LG = 2560, OFF_LGP = 3072, OFF_WGT = 4096, OFF_AB3 = 4608, OFF_RI = 4624,
    OFF_XB = 5664, OFF_HB = 5664 + 67584;
static constexpr int XS = 264, HS = 136;              // strides in halfs (both conflict-free)
static constexpr uint32_t SMEM_BYTES = OFF_HB + 128 * HS * 2;   // 108064

// ---- PTX helpers ----
DEVFN uint32_t smem_u32(const void* p) {
    uint32_t a;
    asm("{ .reg .u64 t; cvta.to.shared.u64 t, %1; cvt.u32.u64 %0, t; }" : "=r"(a) : "l"(p));
    return a;
}
DEVFN void ldm4(uint32_t* r, uint32_t a) {
    asm volatile("ldmatrix.sync.aligned.m8n8.x4.shared.b16 {%0,%1,%2,%3}, [%4];"
                 : "=r"(r[0]), "=r"(r[1]), "=r"(r[2]), "=r"(r[3]) : "r"(a));
}
DEVFN void mma16816(float* c, const uint32_t* a, uint32_t b0, uint32_t b1) {
    asm volatile("mma.sync.aligned.m16n8k16.row.col.f32.f16.f16.f32 "
                 "{%0,%1,%2,%3}, {%4,%5,%6,%7}, {%8,%9}, {%0,%1,%2,%3};"
                 : "+f"(c[0]), "+f"(c[1]), "+f"(c[2]), "+f"(c[3])
                 : "r"(a[0]), "r"(a[1]), "r"(a[2]), "r"(a[3]), "r"(b0), "r"(b1));
}
DEVFN uint32_t pack2(float a, float b) {
    __half2 h = __floats2half2_rn(a, b);
    return *(uint32_t*)&h;
}

// GEMM for 8 warps (4mg x 2ng): warp = 32 rows x 64 cols (8 nt). acc[mf][nt][e].
// Paired-uint4 B fragments from gmem with register double-buffer prefetch.
template<int K, int AST, bool ACC>
DEVFN void gemm8(uint32_t aAbase, const uint2* __restrict__ F,
                 float (&acc)[2][8][4], int lane, int mg, int ng) {
    constexpr int KS = K / 16;
    uint32_t aA = aAbase + (uint32_t)((mg * 32 + ((lane >> 3) & 1) * 8 + (lane & 7)) * AST
                                      + (lane >> 4) * 8) * 2;
    const uint4* Fw = (const uint4*)F + (ng * 4) * 32 + lane;
    if (!ACC) {
        #pragma unroll
        for (int m = 0; m < 2; m++)
            #pragma unroll
            for (int n = 0; n < 8; n++)
                #pragma unroll
                for (int e = 0; e < 4; e++) acc[m][n][e] = 0.f;
    }
    uint4 bf[4], bn[4];
    #pragma unroll
    for (int j = 0; j < 4; j++) bf[j] = __ldg(Fw + j * 32);
    #pragma unroll 1
    for (int ks = 0; ks < KS; ks++) {
        if (ks + 1 < KS) {
            #pragma unroll
            for (int j = 0; j < 4; j++) bn[j] = __ldg(Fw + (ks + 1) * 256 + j * 32);
        }
        uint32_t a0[4], a1[4];
        ldm4(a0, aA + ks * 32);
        ldm4(a1, aA + 16 * AST * 2 + ks * 32);
        #pragma unroll
        for (int j = 0; j < 4; j++) {
            mma16816(acc[0][2 * j],     a0, bf[j].x, bf[j].y);
            mma16816(acc[1][2 * j],     a1, bf[j].x, bf[j].y);
            mma16816(acc[0][2 * j + 1], a0, bf[j].z, bf[j].w);
            mma16816(acc[1][2 * j + 1], a1, bf[j].z, bf[j].w);
        }
        #pragma unroll
        for (int j = 0; j < 4; j++) bf[j] = bn[j];
    }
}

// ===== prepass: r12 (64) || ua2e cvt (128) || selfA1 (512) || pack (128) =====
__global__ void k_prep(const float* __restrict__ u2e, const float* __restrict__ ua2e,
                       const float* __restrict__ r2e, const float* __restrict__ W1,
                       const float* __restrict__ b1, const int* __restrict__ nodes,
                       const float* __restrict__ A1, const float* __restrict__ ab1,
                       const float* __restrict__ W2, const float* __restrict__ A2) {
    __shared__ float sh[8 * 128];
    int b = blockIdx.x, tid = threadIdx.x;
    if (b < 64) {                       // r12: b = t*32+i -> fp16 R12h row (stride 256)
        int t = b >> 5, i = b & 31, c = tid;
        if (c < 128) sh[c] = r2e[i * 128 + c];
        __syncthreads();
        float acc = (t == 0) ? b1[c] : 0.f;
        #pragma unroll 4
        for (int k = 0; k < 128; k++) acc += sh[k] * W1[(t * 128 + k) * 256 + c];
        g_R12h[(t * 32 + i) * 256 + c] = __float2half_rn(acc);
    } else if (b < 192) {               // ua2e convert (2.56 MB), 128 blocks
        int st = 128 * 256, t0 = (b - 64) * 256 + tid;
        const float4* s2 = (const float4*)ua2e;  __half2* d2 = (__half2*)g_ua2e_h;
        for (int i = t0; i < NA * DIM / 4; i += st) {
            float4 v = s2[i];
            d2[2 * i] = __floats2half2_rn(v.x, v.y); d2[2 * i + 1] = __floats2half2_rn(v.z, v.w);
        }
    } else if (b < 704) {               // selfA1: warp-per-node, 512 blocks x 8 warps
        int w = tid >> 5, lane = tid & 31;
        int n = (b - 192) * 8 + w, nd = nodes[n];
        *(float4*)&sh[w * 128 + lane * 4] = *(const float4*)(u2e + (size_t)nd * 128 + lane * 4);
        __syncwarp();
        float4 acc = *(const float4*)(ab1 + lane * 4);
        const float4* A1b = (const float4*)(A1 + 16384) + lane;
        #pragma unroll 8
        for (int k = 0; k < 128; k++) {
            float s = sh[w * 128 + k];
            float4 a4 = __ldg(A1b + k * 32);
            acc.x += s * a4.x; acc.y += s * a4.y; acc.z += s * a4.z; acc.w += s * a4.w;
        }
        *(float4*)(g_selfA1 + (size_t)n * 128 + lane * 4) = acc;
    } else {                            // pack: 128 blocks x 256 = 32768 ids
        int id = (b - 704) * 256 + tid;
        int table, rem, h = 0;
        if (id < 16384)      { table = 1; h = id / 8192; rem = id % 8192; }
        else if (id < 24576) { table = 2; rem = id - 16384; }
        else if (id < 28672) { table = 3; rem = id - 24576; }
        else                 { table = 4; rem = id - 28672; }
        int lane = rem & 31, nb = (rem >> 5) & 15, ks = rem >> 9;
        int n = nb * 8 + (lane >> 2), k0 = ks * 16 + (lane & 3) * 2;
        float v[4];
        #pragma unroll
        for (int j = 0; j < 4; j++) {
            int k = k0 + (j >> 1) * 8 + (j & 1);
            float val;
            if (table == 1)      val = W1[(256 + k) * 256 + h * 128 + n];
            else if (table == 2) val = W2[k * 128 + n];
            else if (table == 3) val = A1[k * 128 + n];
            else                 val = A2[k * 128 + n];
            v[j] = val;
        }
        uint2 fr = make_uint2(pack2(v[0], v[1]), pack2(v[2], v[3]));
        int sidx = ks * 512 + (nb >> 1) * 64 + lane * 2 + (nb & 1);
        if (table == 1)      g_FG1[h * 8192 + sidx] = fr;
        else if (table == 2) g_FG2[sidx] = fr;
        else if (table == 3) g_FG3[sidx] = fr;
        else                 g_FG4[sidx] = fr;
    }
}

// ================= main fused kernel: 256 threads, occupancy 2 =================
__global__ void __launch_bounds__(256, 2)
k_main(const int* __restrict__ prel, const int* __restrict__ pnbr,
       const int* __restrict__ attrs, const float* __restrict__ u2e,
       const float* __restrict__ b2, const float* __restrict__ ab2,
       const float* __restrict__ A3, const float* __restrict__ ab3,
       float* __restrict__ out) {
    extern __shared__ char sm[];
    const uint32_t sb = smem_u32(sm);
    const int tid = threadIdx.x, wid = tid >> 5, lane = tid & 31;
    const int mg = wid >> 1, ng = wid & 1;
    const int tile = blockIdx.x;

    float* b2s  = (float*)(sm + OFF_B2S);
    float* ab2s = (float*)(sm + OFF_AB2);
    float* A3s  = (float*)(sm + OFF_A3);
    float* SA   = (float*)(sm + OFF_SA);
    float* LG   = (float*)(sm + OFF_LG);
    float* LGP  = (float*)(sm + OFF_LGP);
    float* wgs  = (float*)(sm + OFF_WGT);
    int2*  RIs  = (int2*)(sm + OFF_RI);
    char*  XB   = sm + OFF_XB;
    char*  HB   = sm + OFF_HB;
    const uint32_t aXB = sb + OFF_XB, aHB = sb + OFF_HB;

    if (tid < 128) { b2s[tid] = b2[tid]; ab2s[tid] = ab2[tid]; A3s[tid] = A3[tid]; }
    if (tid == 0) *(float*)(sm + OFF_AB3) = ab3[0];
    SA[tid] = g_selfA1[(size_t)tile * 256 + tid];

    // ---- gather X = [ne(128) | ae(128)]: warp-per-row, 16 rows/warp ----
    {
        #pragma unroll 1
        for (int s8 = 0; s8 < 16; s8++) {
            int row = wid * 16 + s8, p = tile * 128 + row;
            char* XR = XB + row * (XS * 2);
            int nbr = __ldg(pnbr + p);
            float4 v = __ldg((const float4*)(u2e + (size_t)nbr * 128) + lane);
            *(uint2*)(XR + lane * 8) = make_uint2(pack2(v.x, v.y), pack2(v.z, v.w));
            const int4* ap = (const int4*)(attrs + (size_t)p * 8);
            int4 a0v = __ldg(ap), a1v = __ldg(ap + 1);
            int at[8];
            at[0]=a0v.x; at[1]=a0v.y; at[2]=a0v.z; at[3]=a0v.w;
            at[4]=a1v.x; at[5]=a1v.y; at[6]=a1v.z; at[7]=a1v.w;
            uint2 d[8];
            #pragma unroll
            for (int a = 0; a < 8; a++)
                d[a] = __ldg((const uint2*)(g_ua2e_h + (size_t)at[a] * 128) + lane);
            float2 s0 = make_float2(0.f, 0.f), s1 = make_float2(0.f, 0.f);
            #pragma unroll
            for (int a = 0; a < 8; a++) {
                float2 f0 = __half22float2(*(__half2*)&d[a].x);
                float2 f1 = __half22float2(*(__half2*)&d[a].y);
                s0.x += f0.x; s0.y += f0.y; s1.x += f1.x; s1.y += f1.y;
            }
            *(uint2*)(XR + 256 + lane * 8) = make_uint2(pack2(s0.x, s0.y), pack2(s1.x, s1.y));
            if (lane == 0) {
                int r0 = __ldg(prel + p * 2), r1 = __ldg(prel + p * 2 + 1);
                RIs[row] = make_int2(r0, 32 + r1);
            }
        }
    }
    __syncthreads();

    float acc[2][8][4];

    // G1b: X @ W1'[cols 128-255] -> raw fp16 -> HB (disjoint from X, no sync needed)
    gemm8<256, XS, false>(aXB, g_FG1 + 8192, acc, lane, mg, ng);
    #pragma unroll
    for (int mf = 0; mf < 2; mf++) {
        int row = mg * 32 + mf * 16 + (lane >> 2);
        #pragma unroll
        for (int nt = 0; nt < 8; nt++) {
            int col = ng * 64 + nt * 8 + (lane & 3) * 2;
            *(__half2*)(HB + (row * HS + col) * 2)       = __floats2half2_rn(acc[mf][nt][0], acc[mf][nt][1]);
            *(__half2*)(HB + ((row + 8) * HS + col) * 2) = __floats2half2_rn(acc[mf][nt][2], acc[mf][nt][3]);
        }
    }
    // G1a: X @ W1'[cols 0-127]
    gemm8<256, XS, false>(aXB, g_FG1, acc, lane, mg, ng);
    __syncthreads();   // all X reads complete
    #pragma unroll
    for (int mf = 0; mf < 2; mf++) {
        int row = mg * 32 + mf * 16 + (lane >> 2);
        #pragma unroll
        for (int nt = 0; nt < 8; nt++) {
            int col = ng * 64 + nt * 8 + (lane & 3) * 2;
            *(__half2*)(XB + (row * XS + col) * 2)       = __floats2half2_rn(acc[mf][nt][0], acc[mf][nt][1]);
            *(__half2*)(XB + ((row + 8) * XS + col) * 2) = __floats2half2_rn(acc[mf][nt][2], acc[mf][nt][3]);
        }
    }
    __syncthreads();

    // R12 + relu pass: warp-per-row, coalesced; h1a in XB cols0-127, h1b in HB
    {
        #pragma unroll 1
        for (int s8 = 0; s8 < 16; s8++) {
            int row = wid * 16 + s8;
            int2 ra = RIs[row];
            const uint2* Ra = (const uint2*)(g_R12h + ra.x * 256);
            const uint2* Rb = (const uint2*)(g_R12h + ra.y * 256);
            // a-half: cols lane*4..+3
            uint2 xa = *(uint2*)(XB + (row * XS + lane * 4) * 2);
            uint2 qa = __ldg(Ra + lane), qb = __ldg(Rb + lane);
            {
                float2 x0 = __half22float2(*(__half2*)&xa.x), x1 = __half22float2(*(__half2*)&xa.y);
                float2 a0 = __half22float2(*(__half2*)&qa.x), a1 = __half22float2(*(__half2*)&qa.y);
                float2 b0 = __half22float2(*(__half2*)&qb.x), b1 = __half22float2(*(__half2*)&qb.y);
                *(uint2*)(XB + (row * XS + lane * 4) * 2) = make_uint2(
                    pack2(fmaxf(x0.x + a0.x + b0.x, 0.f), fmaxf(x0.y + a0.y + b0.y, 0.f)),
                    pack2(fmaxf(x1.x + a1.x + b1.x, 0.f), fmaxf(x1.y + a1.y + b1.y, 0.f)));
            }
            // b-half
            uint2 xb = *(uint2*)(HB + (row * HS + lane * 4) * 2);
            uint2 qc = __ldg(Ra + 32 + lane), qd = __ldg(Rb + 32 + lane);
            {
                float2 x0 = __half22float2(*(__half2*)&xb.x), x1 = __half22float2(*(__half2*)&xb.y);
                float2 a0 = __half22float2(*(__half2*)&qc.x), a1 = __half22float2(*(__half2*)&qc.y);
                float2 b0 = __half22float2(*(__half2*)&qd.x), b1 = __half22float2(*(__half2*)&qd.y);
                *(uint2*)(HB + (row * HS + lane * 4) * 2) = make_uint2(
                    pack2(fmaxf(x0.x + a0.x + b0.x, 0.f), fmaxf(x0.y + a0.y + b0.y, 0.f)),
                    pack2(fmaxf(x1.x + a1.x + b1.x, 0.f), fmaxf(x1.y + a1.y + b1.y, 0.f)));
            }
        }
    }
    __syncthreads();

    // G2 split-K: h1a @ W2[0:128] + h1b @ W2[128:256]
    gemm8<128, XS, false>(aXB, g_FG2, acc, lane, mg, ng);
    gemm8<128, HS, true>(aHB, g_FG2 + 4096, acc, lane, mg, ng);
    __syncthreads();
    // epilogue2: h = relu(acc + b2) -> fp16 XB cols 0-127
    #pragma unroll
    for (int mf = 0; mf < 2; mf++) {
        int row = mg * 32 + mf * 16 + (lane >> 2);
        #pragma unroll
        for (int nt = 0; nt < 8; nt++) {
            int col = ng * 64 + nt * 8 + (lane & 3) * 2;
            *(__half2*)(XB + (row * XS + col) * 2) = __floats2half2_rn(
                fmaxf(acc[mf][nt][0] + b2s[col], 0.f), fmaxf(acc[mf][nt][1] + b2s[col + 1], 0.f));
            *(__half2*)(XB + ((row + 8) * XS + col) * 2) = __floats2half2_rn(
                fmaxf(acc[mf][nt][2] + b2s[col], 0.f), fmaxf(acc[mf][nt][3] + b2s[col + 1], 0.f));
        }
    }
    __syncthreads();
    // G3: h @ A1top -> a1 = relu(+selfA1) -> XB cols 128-255 (disjoint from G3 reads)
    gemm8<128, XS, false>(aXB, g_FG3, acc, lane, mg, ng);
    {
        int node = mg >> 1;
        #pragma unroll
        for (int mf = 0; mf < 2; mf++) {
            int row = mg * 32 + mf * 16 + (lane >> 2);
            #pragma unroll
            for (int nt = 0; nt < 8; nt++) {
                int col = ng * 64 + nt * 8 + (lane & 3) * 2;
                float s0 = SA[node * 128 + col], s1 = SA[node * 128 + col + 1];
                *(__half2*)(XB + (row * XS + col + 128) * 2) = __floats2half2_rn(
                    fmaxf(acc[mf][nt][0] + s0, 0.f), fmaxf(acc[mf][nt][1] + s1, 0.f));
                *(__half2*)(XB + ((row + 8) * XS + col + 128) * 2) = __floats2half2_rn(
                    fmaxf(acc[mf][nt][2] + s0, 0.f), fmaxf(acc[mf][nt][3] + s1, 0.f));
            }
        }
    }
    __syncthreads();
    // G4: a1 @ A2 -> logits
    gemm8<128, XS, false>(aXB + 256, g_FG4, acc, lane, mg, ng);
    {
        float lp[4] = {0.f, 0.f, 0.f, 0.f};
        #pragma unroll
        for (int mf = 0; mf < 2; mf++)
            #pragma unroll
            for (int nt = 0; nt < 8; nt++) {
                int col = ng * 64 + nt * 8 + (lane & 3) * 2;
                float a30 = A3s[col], a31 = A3s[col + 1];
                float c0 = ab2s[col], c1 = ab2s[col + 1];
                lp[mf * 2 + 0] += fmaxf(acc[mf][nt][0] + c0, 0.f) * a30
                                + fmaxf(acc[mf][nt][1] + c1, 0.f) * a31;
                lp[mf * 2 + 1] += fmaxf(acc[mf][nt][2] + c0, 0.f) * a30
                                + fmaxf(acc[mf][nt][3] + c1, 0.f) * a31;
            }
        #pragma unroll
        for (int j = 0; j < 4; j++) {
            lp[j] += __shfl_xor_sync(0xffffffffu, lp[j], 1);
            lp[j] += __shfl_xor_sync(0xffffffffu, lp[j], 2);
        }
        if ((lane & 3) == 0) {
            int rbase = mg * 32 + (lane >> 2);
            #pragma unroll
            for (int j = 0; j < 4; j++)
                LGP[ng * 128 + rbase + j * 8] = lp[j];
        }
    }
    __syncthreads();
    if (tid < 128) LG[tid] = LGP[tid] + LGP[128 + tid] + *(float*)(sm + OFF_AB3);
    __syncthreads();
    if (wid < 2) {   // softmax per node over its 64 logits
        float a = LG[wid * 64 + lane], b = LG[wid * 64 + 32 + lane];
        float m = fmaxf(a, b);
        #pragma unroll
        for (int o = 16; o; o >>= 1) m = fmaxf(m, __shfl_xor_sync(0xffffffffu, m, o));
        float e1 = __expf(a - m), e2 = __expf(b - m), s = e1 + e2;
        #pragma unroll
        for (int o = 16; o; o >>= 1) s += __shfl_xor_sync(0xffffffffu, s, o);
        wgs[wid * 64 + lane] = e1 / s; wgs[wid * 64 + 32 + lane] = e2 / s;
    }
    __syncthreads();

    // weighted reduce from fp16 h in XB cols 0-127
    {
        int node = tid >> 7, col = tid & 127;
        float a = 0.f;
        #pragma unroll 4
        for (int r = 0; r < 64; r++) {
            int row = node * 64 + r;
            float hv = __half2float(*(__half*)(XB + (row * XS + col) * 2));
            a += wgs[row] * hv;
        }
        out[((size_t)tile * 2 + node) * 128 + col] = a;
    }
}

// ================= launch =================
extern "C" void kernel_launch(void* const* d_in, const int* in_sizes, int n_in,
                              void* d_out, int out_size) {
    const int*   nodes = (const int*)  d_in[0];
    const int*   prel  = (const int*)  d_in[1];
    const int*   pnbr  = (const int*)  d_in[2];
    const int*   attrs = (const int*)  d_in[3];
    const float* u2e   = (const float*)d_in[4];
    const float* r2e   = (const float*)d_in[5];
    const float* ua2e  = (const float*)d_in[6];
    const float* W1    = (const float*)d_in[7];
    const float* b1    = (const float*)d_in[8];
    const float* W2    = (const float*)d_in[9];
    const float* b2    = (const float*)d_in[10];
    const float* A1    = (const float*)d_in[11];
    const float* ab1   = (const float*)d_in[12];
    const float* A2    = (const float*)d_in[13];
    const float* ab2   = (const float*)d_in[14];
    const float* A3    = (const float*)d_in[15];
    const float* ab3   = (const float*)d_in[16];
    float* out = (float*)d_out;

    cudaFuncSetAttribute(k_main, cudaFuncAttributeMaxDynamicSharedMemorySize, (int)SMEM_BYTES);

    k_prep<<<832, 256>>>(u2e, ua2e, r2e, W1, b1, nodes, A1, ab1, W2, A2);
    k_main<<<2048, 256, SMEM_BYTES>>>(prel, pnbr, attrs, u2e, b2, ab2, A3, ab3, out);
}